// round 1
// baseline (speedup 1.0000x reference)
#include <cuda_runtime.h>
#include <math.h>

#define D_MODEL 2048
#define NQ 32
#define NKV 8
#define HD 64
#define B_ 2
#define T_ 2048
#define ROWS (B_ * T_)

// Scratch for projected Q, K, V (allocation-free: device globals).
__device__ float g_Q[(size_t)ROWS * NQ * HD];   // [4096, 2048]
__device__ float g_K[(size_t)ROWS * NKV * HD];  // [4096, 512]
__device__ float g_V[(size_t)ROWS * NKV * HD];  // [4096, 512]

// ---------------------------------------------------------------------------
// GEMM: C[M=4096, N] = A[4096, 2048] @ W[2048, N]
// 64x64 tile, BK=16, 256 threads, 4x4 per-thread microtile.
// ---------------------------------------------------------------------------
__global__ __launch_bounds__(256) void gemm64_kernel(
    const float* __restrict__ A, const float* __restrict__ W,
    float* __restrict__ C, int N) {
    __shared__ float As[16][64];  // [k][m]
    __shared__ float Bs[16][64];  // [k][n]

    const int tid = threadIdx.x;
    const int tx = tid & 15;       // 0..15 -> 4 output cols each
    const int ty = tid >> 4;       // 0..15 -> 4 output rows each
    const int m0 = blockIdx.y * 64;
    const int n0 = blockIdx.x * 64;

    // A-load mapping: one float4 per thread: row = tid>>2 (0..63), k-quad = tid&3
    const int arow = tid >> 2;
    const int akq = tid & 3;
    // B-load mapping: one float4 per thread: k = tid>>4 (0..15), n-quad = tid&15
    const int bk = tid >> 4;
    const int bn = tid & 15;

    float acc[4][4];
#pragma unroll
    for (int i = 0; i < 4; i++)
#pragma unroll
        for (int j = 0; j < 4; j++) acc[i][j] = 0.0f;

    for (int k0 = 0; k0 < D_MODEL; k0 += 16) {
        __syncthreads();
        // Load A tile (transposed into [k][m])
        float4 av = *reinterpret_cast<const float4*>(
            A + (size_t)(m0 + arow) * D_MODEL + k0 + akq * 4);
        As[akq * 4 + 0][arow] = av.x;
        As[akq * 4 + 1][arow] = av.y;
        As[akq * 4 + 2][arow] = av.z;
        As[akq * 4 + 3][arow] = av.w;
        // Load B tile
        float4 bv = *reinterpret_cast<const float4*>(
            W + (size_t)(k0 + bk) * N + n0 + bn * 4);
        *reinterpret_cast<float4*>(&Bs[bk][bn * 4]) = bv;
        __syncthreads();

#pragma unroll
        for (int k = 0; k < 16; k++) {
            float4 a = *reinterpret_cast<const float4*>(&As[k][ty * 4]);
            float4 b = *reinterpret_cast<const float4*>(&Bs[k][tx * 4]);
            acc[0][0] += a.x * b.x; acc[0][1] += a.x * b.y;
            acc[0][2] += a.x * b.z; acc[0][3] += a.x * b.w;
            acc[1][0] += a.y * b.x; acc[1][1] += a.y * b.y;
            acc[1][2] += a.y * b.z; acc[1][3] += a.y * b.w;
            acc[2][0] += a.z * b.x; acc[2][1] += a.z * b.y;
            acc[2][2] += a.z * b.z; acc[2][3] += a.z * b.w;
            acc[3][0] += a.w * b.x; acc[3][1] += a.w * b.y;
            acc[3][2] += a.w * b.z; acc[3][3] += a.w * b.w;
        }
    }

#pragma unroll
    for (int i = 0; i < 4; i++) {
        float4 r = make_float4(acc[i][0], acc[i][1], acc[i][2], acc[i][3]);
        *reinterpret_cast<float4*>(
            C + (size_t)(m0 + ty * 4 + i) * N + n0 + tx * 4) = r;
    }
}

// ---------------------------------------------------------------------------
// Causal GQA flash attention.
// Grid: (T/64, NQ, B). Block: 64 threads, one query row per thread.
// Q row and O accumulator in registers; K/V tiles in smem (broadcast reads).
// ---------------------------------------------------------------------------
__global__ __launch_bounds__(64) void attn_kernel(
    const float* __restrict__ Q, const float* __restrict__ K,
    const float* __restrict__ V, float* __restrict__ out) {
    const int qt = blockIdx.x;   // query tile (0..31)
    const int h = blockIdx.y;    // q head (0..31)
    const int b = blockIdx.z;    // batch
    const int kvh = h >> 2;      // GQA group of 4
    const int tid = threadIdx.x;
    const int qi = qt * 64 + tid;  // global query position

    __shared__ float Ks[64][64];  // [key][d]
    __shared__ float Vs[64][64];  // [key][d]
    __shared__ float Ss[64][64];  // [key][query-row]  (conflict-free per-row access)

    // Load Q row into registers, fold in 1/sqrt(64) * log2(e) so the softmax
    // inner loop is pure exp2f.
    const float sc = 0.125f * 1.4426950408889634f;
    float4 q[16];
    {
        const float4* qsrc = reinterpret_cast<const float4*>(
            Q + (size_t)(b * T_ + qi) * (NQ * HD) + h * HD);
#pragma unroll
        for (int i = 0; i < 16; i++) {
            float4 t = qsrc[i];
            t.x *= sc; t.y *= sc; t.z *= sc; t.w *= sc;
            q[i] = t;
        }
    }

    float4 o[16];
#pragma unroll
    for (int i = 0; i < 16; i++) o[i] = make_float4(0.f, 0.f, 0.f, 0.f);
    float m = -1e30f;
    float l = 0.f;

    const float4* kbase = reinterpret_cast<const float4*>(
        K + (size_t)(b * T_) * (NKV * HD) + kvh * HD);
    const float4* vbase = reinterpret_cast<const float4*>(
        V + (size_t)(b * T_) * (NKV * HD) + kvh * HD);
    const int rowstride4 = (NKV * HD) / 4;  // 128 float4 per token row

    for (int jt = 0; jt <= qt; jt++) {
        __syncthreads();
        // Cooperative K/V tile load: 64 keys x 64 dims, float4 granularity.
#pragma unroll
        for (int i = 0; i < 16; i++) {
            int idx = i * 64 + tid;       // 0..1023
            int j = idx >> 4;             // key row
            int d4 = idx & 15;            // float4 within row
            size_t goff = (size_t)(jt * 64 + j) * rowstride4 + d4;
            *reinterpret_cast<float4*>(&Ks[j][d4 * 4]) = kbase[goff];
            *reinterpret_cast<float4*>(&Vs[j][d4 * 4]) = vbase[goff];
        }
        __syncthreads();

        const int jmax = (jt == qt) ? (tid + 1) : 64;  // causal bound
        float mt = m;
#pragma unroll 1
        for (int j = 0; j < 64; j++) {
            const float4* kr = reinterpret_cast<const float4*>(&Ks[j][0]);
            float s0 = 0.f, s1 = 0.f, s2 = 0.f, s3 = 0.f;
#pragma unroll
            for (int d = 0; d < 16; d++) {
                float4 kk = kr[d];
                s0 += q[d].x * kk.x;
                s1 += q[d].y * kk.y;
                s2 += q[d].z * kk.z;
                s3 += q[d].w * kk.w;
            }
            float s = (s0 + s1) + (s2 + s3);
            if (j >= jmax) s = -1e30f;
            Ss[j][tid] = s;
            mt = fmaxf(mt, s);
        }

        const float c = exp2f(m - mt);
        m = mt;
        l *= c;
#pragma unroll
        for (int i = 0; i < 16; i++) {
            o[i].x *= c; o[i].y *= c; o[i].z *= c; o[i].w *= c;
        }

#pragma unroll 1
        for (int j = 0; j < 64; j++) {
            float p = exp2f(Ss[j][tid] - m);
            l += p;
            const float4* vr = reinterpret_cast<const float4*>(&Vs[j][0]);
#pragma unroll
            for (int d = 0; d < 16; d++) {
                float4 vv = vr[d];
                o[d].x += p * vv.x;
                o[d].y += p * vv.y;
                o[d].z += p * vv.z;
                o[d].w += p * vv.w;
            }
        }
    }

    const float inv = 1.0f / l;
    float4* dst = reinterpret_cast<float4*>(
        out + (size_t)(b * T_ + qi) * (NQ * HD) + h * HD);
#pragma unroll
    for (int i = 0; i < 16; i++) {
        float4 t = o[i];
        t.x *= inv; t.y *= inv; t.z *= inv; t.w *= inv;
        dst[i] = t;
    }
}

// ---------------------------------------------------------------------------
extern "C" void kernel_launch(void* const* d_in, const int* in_sizes, int n_in,
                              void* d_out, int out_size) {
    (void)in_sizes; (void)n_in; (void)out_size;
    const float* x = (const float*)d_in[0];   // [B, T, D_MODEL]
    const float* Wq = (const float*)d_in[1];  // [D_MODEL, NQ*HD]
    const float* Wk = (const float*)d_in[2];  // [D_MODEL, NKV*HD]
    const float* Wv = (const float*)d_in[3];  // [D_MODEL, NKV*HD]
    float* out = (float*)d_out;               // [B, T, NQ*HD]

    float *Qp = nullptr, *Kp = nullptr, *Vp = nullptr;
    cudaGetSymbolAddress((void**)&Qp, g_Q);
    cudaGetSymbolAddress((void**)&Kp, g_K);
    cudaGetSymbolAddress((void**)&Vp, g_V);

    // Projections
    {
        dim3 gq((NQ * HD) / 64, ROWS / 64);
        gemm64_kernel<<<gq, 256>>>(x, Wq, Qp, NQ * HD);
        dim3 gk((NKV * HD) / 64, ROWS / 64);
        gemm64_kernel<<<gk, 256>>>(x, Wk, Kp, NKV * HD);
        gemm64_kernel<<<gk, 256>>>(x, Wv, Vp, NKV * HD);
    }

    // Causal GQA attention
    {
        dim3 ga(T_ / 64, NQ, B_);
        attn_kernel<<<ga, 64>>>(Qp, Kp, Vp, out);
    }
}

// round 3
// speedup vs baseline: 1.5306x; 1.5306x over previous
#include <cuda_runtime.h>
#include <math.h>
#include <stdint.h>

#define D_MODEL 2048
#define NQ 32
#define NKV 8
#define HD 64
#define B_ 2
#define T_ 2048
#define ROWS (B_ * T_)

// Scratch (allocation-free device globals).
__device__ float g_Q[(size_t)ROWS * NQ * HD];    // [4096, 2048]
__device__ float g_K[(size_t)ROWS * NKV * HD];   // [4096, 512]
__device__ float g_V[(size_t)ROWS * NKV * HD];   // [4096, 512]
// Transposed weights: Wq^T [2048,2048], Wk^T [512,2048], Wv^T [512,2048]
__device__ float g_Wt[(size_t)2048 * 2048 + 2 * (size_t)512 * 2048];

__device__ __forceinline__ uint32_t f2tf32(float f) {
    uint32_t r;
    asm("cvt.rna.tf32.f32 %0, %1;" : "=r"(r) : "f"(f));
    return r;
}

__device__ __forceinline__ void mma_tf32(float* d, const uint32_t* a,
                                         const uint32_t* b) {
    asm volatile(
        "mma.sync.aligned.m16n8k8.row.col.f32.tf32.tf32.f32 "
        "{%0,%1,%2,%3}, {%4,%5,%6,%7}, {%8,%9}, {%0,%1,%2,%3};"
        : "+f"(d[0]), "+f"(d[1]), "+f"(d[2]), "+f"(d[3])
        : "r"(a[0]), "r"(a[1]), "r"(a[2]), "r"(a[3]),
          "r"(b[0]), "r"(b[1]));
}

// ============================ Transpose ============================
// W: [2048, N] row-major -> Wt: [N, 2048] row-major
__global__ __launch_bounds__(256) void transpose_kernel(
    const float* __restrict__ W, float* __restrict__ Wt, int N) {
    __shared__ float t[32][33];
    const int bx = blockIdx.x * 32;  // n
    const int by = blockIdx.y * 32;  // k
    const int x = threadIdx.x;
    const int y = threadIdx.y;
#pragma unroll
    for (int i = 0; i < 32; i += 8)
        t[y + i][x] = W[(size_t)(by + y + i) * N + bx + x];
    __syncthreads();
#pragma unroll
    for (int i = 0; i < 32; i += 8)
        Wt[(size_t)(bx + y + i) * 2048 + by + x] = t[x][y + i];
}

// ============================ mma.sync tf32 GEMM ============================
// C[M=4096, N] = A[4096,2048] @ Bt[N,2048]^T
// Tile 128x128x32, 256 threads, warp grid 2(m) x 4(n), warp tile 64x32.
#define BM 128
#define BN 128
#define BK 32
#define PITCH 36   // conflict-free: (g*36+c) mod 32 = g*4+c covers all banks

__global__ __launch_bounds__(256) void gemm_mma(
    const float* __restrict__ A, const float* __restrict__ Bt,
    float* __restrict__ C, int N) {
    __shared__ float As[BM][PITCH];
    __shared__ float Bs[BN][PITCH];

    const int tid = threadIdx.x;
    const int lane = tid & 31;
    const int warp = tid >> 5;
    const int wm = warp & 1;   // 0..1  (64 rows each)
    const int wn = warp >> 1;  // 0..3  (32 cols each)
    const int m0 = blockIdx.y * BM;
    const int n0 = blockIdx.x * BN;
    const int grp = lane >> 2;   // 0..7
    const int tk = lane & 3;     // 0..3

    float acc[4][4][4];
#pragma unroll
    for (int i = 0; i < 4; i++)
#pragma unroll
        for (int j = 0; j < 4; j++)
#pragma unroll
            for (int v = 0; v < 4; v++) acc[i][j][v] = 0.f;

    // Global load mapping: 128 rows x 8 float4 = 1024 float4; 4 per thread.
    const int grow = tid >> 1;            // unused; keep mapping below
    (void)grow;

    for (int k0 = 0; k0 < D_MODEL; k0 += BK) {
        __syncthreads();
#pragma unroll
        for (int i = 0; i < 4; i++) {
            int idx = i * 256 + tid;
            int r = idx >> 3, q = idx & 7;
            float4 va = *reinterpret_cast<const float4*>(
                A + (size_t)(m0 + r) * D_MODEL + k0 + q * 4);
            float4 sa;
            sa.x = __uint_as_float(f2tf32(va.x));
            sa.y = __uint_as_float(f2tf32(va.y));
            sa.z = __uint_as_float(f2tf32(va.z));
            sa.w = __uint_as_float(f2tf32(va.w));
            *reinterpret_cast<float4*>(&As[r][q * 4]) = sa;

            float4 vb = *reinterpret_cast<const float4*>(
                Bt + (size_t)(n0 + r) * D_MODEL + k0 + q * 4);
            float4 sb;
            sb.x = __uint_as_float(f2tf32(vb.x));
            sb.y = __uint_as_float(f2tf32(vb.y));
            sb.z = __uint_as_float(f2tf32(vb.z));
            sb.w = __uint_as_float(f2tf32(vb.w));
            *reinterpret_cast<float4*>(&Bs[r][q * 4]) = sb;
        }
        __syncthreads();

#pragma unroll
        for (int ks = 0; ks < 4; ks++) {
            const int kk = ks * 8;
            uint32_t a[4][4], b[4][2];
#pragma unroll
            for (int mf = 0; mf < 4; mf++) {
                int r = wm * 64 + mf * 16 + grp;
                a[mf][0] = __float_as_uint(As[r][kk + tk]);
                a[mf][1] = __float_as_uint(As[r + 8][kk + tk]);
                a[mf][2] = __float_as_uint(As[r][kk + tk + 4]);
                a[mf][3] = __float_as_uint(As[r + 8][kk + tk + 4]);
            }
#pragma unroll
            for (int nf = 0; nf < 4; nf++) {
                int cn = wn * 32 + nf * 8 + grp;
                b[nf][0] = __float_as_uint(Bs[cn][kk + tk]);
                b[nf][1] = __float_as_uint(Bs[cn][kk + tk + 4]);
            }
#pragma unroll
            for (int mf = 0; mf < 4; mf++)
#pragma unroll
                for (int nf = 0; nf < 4; nf++)
                    mma_tf32(acc[mf][nf], a[mf], b[nf]);
        }
    }

    // Epilogue: c0,c1 at (row=grp, col=2*tk, 2*tk+1); c2,c3 at row=grp+8.
#pragma unroll
    for (int mf = 0; mf < 4; mf++) {
#pragma unroll
        for (int nf = 0; nf < 4; nf++) {
            int r = m0 + wm * 64 + mf * 16 + grp;
            int c = n0 + wn * 32 + nf * 8 + 2 * tk;
            float2 lo = make_float2(acc[mf][nf][0], acc[mf][nf][1]);
            float2 hi = make_float2(acc[mf][nf][2], acc[mf][nf][3]);
            *reinterpret_cast<float2*>(C + (size_t)r * N + c) = lo;
            *reinterpret_cast<float2*>(C + (size_t)(r + 8) * N + c) = hi;
        }
    }
}

// ============================ Attention (fp32, unchanged) ============================
__global__ __launch_bounds__(64) void attn_kernel(
    const float* __restrict__ Q, const float* __restrict__ K,
    const float* __restrict__ V, float* __restrict__ out) {
    const int qt = blockIdx.x;
    const int h = blockIdx.y;
    const int b = blockIdx.z;
    const int kvh = h >> 2;
    const int tid = threadIdx.x;
    const int qi = qt * 64 + tid;

    __shared__ float Ks[64][64];
    __shared__ float Vs[64][64];
    __shared__ float Ss[64][64];

    const float sc = 0.125f * 1.4426950408889634f;
    float4 q[16];
    {
        const float4* qsrc = reinterpret_cast<const float4*>(
            Q + (size_t)(b * T_ + qi) * (NQ * HD) + h * HD);
#pragma unroll
        for (int i = 0; i < 16; i++) {
            float4 t = qsrc[i];
            t.x *= sc; t.y *= sc; t.z *= sc; t.w *= sc;
            q[i] = t;
        }
    }

    float4 o[16];
#pragma unroll
    for (int i = 0; i < 16; i++) o[i] = make_float4(0.f, 0.f, 0.f, 0.f);
    float m = -1e30f;
    float l = 0.f;

    const float4* kbase = reinterpret_cast<const float4*>(
        K + (size_t)(b * T_) * (NKV * HD) + kvh * HD);
    const float4* vbase = reinterpret_cast<const float4*>(
        V + (size_t)(b * T_) * (NKV * HD) + kvh * HD);
    const int rowstride4 = (NKV * HD) / 4;

    for (int jt = 0; jt <= qt; jt++) {
        __syncthreads();
#pragma unroll
        for (int i = 0; i < 16; i++) {
            int idx = i * 64 + tid;
            int j = idx >> 4;
            int d4 = idx & 15;
            size_t goff = (size_t)(jt * 64 + j) * rowstride4 + d4;
            *reinterpret_cast<float4*>(&Ks[j][d4 * 4]) = kbase[goff];
            *reinterpret_cast<float4*>(&Vs[j][d4 * 4]) = vbase[goff];
        }
        __syncthreads();

        const int jmax = (jt == qt) ? (tid + 1) : 64;
        float mt = m;
#pragma unroll 1
        for (int j = 0; j < 64; j++) {
            const float4* kr = reinterpret_cast<const float4*>(&Ks[j][0]);
            float s0 = 0.f, s1 = 0.f, s2 = 0.f, s3 = 0.f;
#pragma unroll
            for (int d = 0; d < 16; d++) {
                float4 kk = kr[d];
                s0 += q[d].x * kk.x;
                s1 += q[d].y * kk.y;
                s2 += q[d].z * kk.z;
                s3 += q[d].w * kk.w;
            }
            float s = (s0 + s1) + (s2 + s3);
            if (j >= jmax) s = -1e30f;
            Ss[j][tid] = s;
            mt = fmaxf(mt, s);
        }

        const float c = exp2f(m - mt);
        m = mt;
        l *= c;
#pragma unroll
        for (int i = 0; i < 16; i++) {
            o[i].x *= c; o[i].y *= c; o[i].z *= c; o[i].w *= c;
        }

#pragma unroll 1
        for (int j = 0; j < 64; j++) {
            float p = exp2f(Ss[j][tid] - m);
            l += p;
            const float4* vr = reinterpret_cast<const float4*>(&Vs[j][0]);
#pragma unroll
            for (int d = 0; d < 16; d++) {
                float4 vv = vr[d];
                o[d].x += p * vv.x;
                o[d].y += p * vv.y;
                o[d].z += p * vv.z;
                o[d].w += p * vv.w;
            }
        }
    }

    const float inv = 1.0f / l;
    float4* dst = reinterpret_cast<float4*>(
        out + (size_t)(b * T_ + qi) * (NQ * HD) + h * HD);
#pragma unroll
    for (int i = 0; i < 16; i++) {
        float4 t = o[i];
        t.x *= inv; t.y *= inv; t.z *= inv; t.w *= inv;
        dst[i] = t;
    }
}

// ============================ Launch ============================
extern "C" void kernel_launch(void* const* d_in, const int* in_sizes, int n_in,
                              void* d_out, int out_size) {
    (void)in_sizes; (void)n_in; (void)out_size;
    const float* x = (const float*)d_in[0];
    const float* Wq = (const float*)d_in[1];
    const float* Wk = (const float*)d_in[2];
    const float* Wv = (const float*)d_in[3];
    float* out = (float*)d_out;

    float *Qp = nullptr, *Kp = nullptr, *Vp = nullptr, *Wt = nullptr;
    cudaGetSymbolAddress((void**)&Qp, g_Q);
    cudaGetSymbolAddress((void**)&Kp, g_K);
    cudaGetSymbolAddress((void**)&Vp, g_V);
    cudaGetSymbolAddress((void**)&Wt, g_Wt);
    float* Wtq = Wt;
    float* Wtk = Wt + (size_t)2048 * 2048;
    float* Wtv = Wtk + (size_t)512 * 2048;

    // Transpose weights: [2048, N] -> [N, 2048]
    transpose_kernel<<<dim3(2048 / 32, 2048 / 32), dim3(32, 8)>>>(Wq, Wtq, 2048);
    transpose_kernel<<<dim3(512 / 32, 2048 / 32), dim3(32, 8)>>>(Wk, Wtk, 512);
    transpose_kernel<<<dim3(512 / 32, 2048 / 32), dim3(32, 8)>>>(Wv, Wtv, 512);

    // Projections via mma.sync tf32
    gemm_mma<<<dim3(2048 / BN, ROWS / BM), 256>>>(x, Wtq, Qp, 2048);
    gemm_mma<<<dim3(512 / BN, ROWS / BM), 256>>>(x, Wtk, Kp, 512);
    gemm_mma<<<dim3(512 / BN, ROWS / BM), 256>>>(x, Wtv, Vp, 512);

    // Causal GQA attention
    dim3 ga(T_ / 64, NQ, B_);
    attn_kernel<<<ga, 64>>>(Qp, Kp, Vp, out);
}

// round 4
// speedup vs baseline: 3.2709x; 2.1371x over previous
#include <cuda_runtime.h>
#include <math.h>
#include <stdint.h>

#define D_MODEL 2048
#define NQ 32
#define NKV 8
#define HD 64
#define B_ 2
#define T_ 2048
#define ROWS (B_ * T_)

// Scratch (allocation-free device globals).
__device__ float g_Q[(size_t)ROWS * NQ * HD];    // [4096, 2048]
__device__ float g_K[(size_t)ROWS * NKV * HD];   // [4096, 512]
__device__ float g_V[(size_t)ROWS * NKV * HD];   // [4096, 512]
__device__ float g_Wt[(size_t)2048 * 2048 + 2 * (size_t)512 * 2048];

__device__ __forceinline__ uint32_t f2tf32(float f) {
    uint32_t r;
    asm("cvt.rna.tf32.f32 %0, %1;" : "=r"(r) : "f"(f));
    return r;
}

__device__ __forceinline__ void mma_tf32(float* d, const uint32_t* a,
                                         const uint32_t* b) {
    asm volatile(
        "mma.sync.aligned.m16n8k8.row.col.f32.tf32.tf32.f32 "
        "{%0,%1,%2,%3}, {%4,%5,%6,%7}, {%8,%9}, {%0,%1,%2,%3};"
        : "+f"(d[0]), "+f"(d[1]), "+f"(d[2]), "+f"(d[3])
        : "r"(a[0]), "r"(a[1]), "r"(a[2]), "r"(a[3]),
          "r"(b[0]), "r"(b[1]));
}

// ============================ Transpose ============================
__global__ __launch_bounds__(256) void transpose_kernel(
    const float* __restrict__ W, float* __restrict__ Wt, int N) {
    __shared__ float t[32][33];
    const int bx = blockIdx.x * 32;
    const int by = blockIdx.y * 32;
    const int x = threadIdx.x;
    const int y = threadIdx.y;
#pragma unroll
    for (int i = 0; i < 32; i += 8)
        t[y + i][x] = W[(size_t)(by + y + i) * N + bx + x];
    __syncthreads();
#pragma unroll
    for (int i = 0; i < 32; i += 8)
        Wt[(size_t)(bx + y + i) * 2048 + by + x] = t[x][y + i];
}

// ============================ mma.sync tf32 GEMM ============================
#define BM 128
#define BN 128
#define BK 32
#define PITCH 36

__global__ __launch_bounds__(256) void gemm_mma(
    const float* __restrict__ A, const float* __restrict__ Bt,
    float* __restrict__ C, int N) {
    __shared__ float As[BM][PITCH];
    __shared__ float Bs[BN][PITCH];

    const int tid = threadIdx.x;
    const int lane = tid & 31;
    const int warp = tid >> 5;
    const int wm = warp & 1;
    const int wn = warp >> 1;
    const int m0 = blockIdx.y * BM;
    const int n0 = blockIdx.x * BN;
    const int grp = lane >> 2;
    const int tk = lane & 3;

    float acc[4][4][4];
#pragma unroll
    for (int i = 0; i < 4; i++)
#pragma unroll
        for (int j = 0; j < 4; j++)
#pragma unroll
            for (int v = 0; v < 4; v++) acc[i][j][v] = 0.f;

    for (int k0 = 0; k0 < D_MODEL; k0 += BK) {
        __syncthreads();
#pragma unroll
        for (int i = 0; i < 4; i++) {
            int idx = i * 256 + tid;
            int r = idx >> 3, q = idx & 7;
            float4 va = *reinterpret_cast<const float4*>(
                A + (size_t)(m0 + r) * D_MODEL + k0 + q * 4);
            float4 sa;
            sa.x = __uint_as_float(f2tf32(va.x));
            sa.y = __uint_as_float(f2tf32(va.y));
            sa.z = __uint_as_float(f2tf32(va.z));
            sa.w = __uint_as_float(f2tf32(va.w));
            *reinterpret_cast<float4*>(&As[r][q * 4]) = sa;

            float4 vb = *reinterpret_cast<const float4*>(
                Bt + (size_t)(n0 + r) * D_MODEL + k0 + q * 4);
            float4 sb;
            sb.x = __uint_as_float(f2tf32(vb.x));
            sb.y = __uint_as_float(f2tf32(vb.y));
            sb.z = __uint_as_float(f2tf32(vb.z));
            sb.w = __uint_as_float(f2tf32(vb.w));
            *reinterpret_cast<float4*>(&Bs[r][q * 4]) = sb;
        }
        __syncthreads();

#pragma unroll
        for (int ks = 0; ks < 4; ks++) {
            const int kk = ks * 8;
            uint32_t a[4][4], b[4][2];
#pragma unroll
            for (int mf = 0; mf < 4; mf++) {
                int r = wm * 64 + mf * 16 + grp;
                a[mf][0] = __float_as_uint(As[r][kk + tk]);
                a[mf][1] = __float_as_uint(As[r + 8][kk + tk]);
                a[mf][2] = __float_as_uint(As[r][kk + tk + 4]);
                a[mf][3] = __float_as_uint(As[r + 8][kk + tk + 4]);
            }
#pragma unroll
            for (int nf = 0; nf < 4; nf++) {
                int cn = wn * 32 + nf * 8 + grp;
                b[nf][0] = __float_as_uint(Bs[cn][kk + tk]);
                b[nf][1] = __float_as_uint(Bs[cn][kk + tk + 4]);
            }
#pragma unroll
            for (int mf = 0; mf < 4; mf++)
#pragma unroll
                for (int nf = 0; nf < 4; nf++)
                    mma_tf32(acc[mf][nf], a[mf], b[nf]);
        }
    }

#pragma unroll
    for (int mf = 0; mf < 4; mf++) {
#pragma unroll
        for (int nf = 0; nf < 4; nf++) {
            int r = m0 + wm * 64 + mf * 16 + grp;
            int c = n0 + wn * 32 + nf * 8 + 2 * tk;
            float2 lo = make_float2(acc[mf][nf][0], acc[mf][nf][1]);
            float2 hi = make_float2(acc[mf][nf][2], acc[mf][nf][3]);
            *reinterpret_cast<float2*>(C + (size_t)r * N + c) = lo;
            *reinterpret_cast<float2*>(C + (size_t)(r + 8) * N + c) = hi;
        }
    }
}

// ============================ Tensor-core attention ============================
// Block: 128 threads (4 warps), 64-query tile; warp w owns rows 16w..16w+15.
// S = Q K^T and O += P V via m16n8k8 tf32; online softmax on fragments.
#define AP 68   // smem pitch (floats): 68 mod 32 == 4 -> conflict-free frags

__global__ __launch_bounds__(128) void attn_mma(
    const float* __restrict__ Q, const float* __restrict__ K,
    const float* __restrict__ V, float* __restrict__ out) {
    extern __shared__ float sm[];
    float* Ks = sm;              // [64][AP]  K tile, [key][d]
    float* Vt = sm + 64 * AP;    // [64][AP]  V tile transposed, [d][key]
    float* Ps = sm + 2 * 64 * AP;  // [64][AP]  P (tf32 bits), [q][key]

    const int qt = blockIdx.x;
    const int h = blockIdx.y;
    const int b = blockIdx.z;
    const int kvh = h >> 2;
    const int tid = threadIdx.x;
    const int lane = tid & 31;
    const int w = tid >> 5;
    const int grp = lane >> 2;
    const int tk = lane & 3;
    const int q0 = qt * 64;
    const int r0 = 16 * w + grp;  // local query row (and r0+8)

    // Q fragments (scale * log2e folded in), kept in registers for all tiles.
    const float sc = 0.125f * 1.4426950408889634f;
    uint32_t qf[8][4];
    {
        const float* qr0 = Q + ((size_t)(b * T_) + q0 + r0) * (NQ * HD) + h * HD;
        const float* qr1 = qr0 + 8 * (NQ * HD);
#pragma unroll
        for (int ks = 0; ks < 8; ks++) {
            qf[ks][0] = f2tf32(qr0[ks * 8 + tk] * sc);
            qf[ks][1] = f2tf32(qr1[ks * 8 + tk] * sc);
            qf[ks][2] = f2tf32(qr0[ks * 8 + tk + 4] * sc);
            qf[ks][3] = f2tf32(qr1[ks * 8 + tk + 4] * sc);
        }
    }

    float of[8][4];
#pragma unroll
    for (int nf = 0; nf < 8; nf++)
#pragma unroll
        for (int v = 0; v < 4; v++) of[nf][v] = 0.f;
    float m0 = -1e30f, m1 = -1e30f, l0 = 0.f, l1 = 0.f;

    const float* kb = K + (size_t)(b * T_) * (NKV * HD) + kvh * HD;
    const float* vb = V + (size_t)(b * T_) * (NKV * HD) + kvh * HD;

    for (int jt = 0; jt <= qt; jt++) {
        __syncthreads();
        // Load K tile [key][d] and V tile transposed [d][key].
#pragma unroll
        for (int i = 0; i < 8; i++) {
            int idx = i * 128 + tid;     // 0..1023
            int key = idx >> 4;          // 0..63
            int q4 = idx & 15;           // float4 within 64-wide row
            size_t go = (size_t)(jt * 64 + key) * (NKV * HD) + q4 * 4;
            float4 kv = *reinterpret_cast<const float4*>(kb + go);
            *reinterpret_cast<float4*>(&Ks[key * AP + q4 * 4]) = kv;
            float4 vv = *reinterpret_cast<const float4*>(vb + go);
            Vt[(q4 * 4 + 0) * AP + key] = vv.x;
            Vt[(q4 * 4 + 1) * AP + key] = vv.y;
            Vt[(q4 * 4 + 2) * AP + key] = vv.z;
            Vt[(q4 * 4 + 3) * AP + key] = vv.w;
        }
        __syncthreads();

        // S = Q K^T  (n = key)
        float sa[8][4];
#pragma unroll
        for (int nf = 0; nf < 8; nf++)
#pragma unroll
            for (int v = 0; v < 4; v++) sa[nf][v] = 0.f;
#pragma unroll
        for (int ks = 0; ks < 8; ks++) {
            const int kk = ks * 8;
#pragma unroll
            for (int nf = 0; nf < 8; nf++) {
                uint32_t bf[2];
                bf[0] = f2tf32(Ks[(8 * nf + grp) * AP + kk + tk]);
                bf[1] = f2tf32(Ks[(8 * nf + grp) * AP + kk + tk + 4]);
                mma_tf32(sa[nf], qf[ks], bf);
            }
        }

        // Causal mask on the diagonal tile.
        if (jt == qt) {
#pragma unroll
            for (int nf = 0; nf < 8; nf++) {
                int c0 = 8 * nf + 2 * tk;
                if (c0 > r0) sa[nf][0] = -1e30f;
                if (c0 + 1 > r0) sa[nf][1] = -1e30f;
                if (c0 > r0 + 8) sa[nf][2] = -1e30f;
                if (c0 + 1 > r0 + 8) sa[nf][3] = -1e30f;
            }
        }

        // Row max (reduce over nf then over the tk quad).
        float mt0 = -1e30f, mt1 = -1e30f;
#pragma unroll
        for (int nf = 0; nf < 8; nf++) {
            mt0 = fmaxf(mt0, fmaxf(sa[nf][0], sa[nf][1]));
            mt1 = fmaxf(mt1, fmaxf(sa[nf][2], sa[nf][3]));
        }
        mt0 = fmaxf(mt0, __shfl_xor_sync(0xffffffffu, mt0, 1));
        mt0 = fmaxf(mt0, __shfl_xor_sync(0xffffffffu, mt0, 2));
        mt1 = fmaxf(mt1, __shfl_xor_sync(0xffffffffu, mt1, 1));
        mt1 = fmaxf(mt1, __shfl_xor_sync(0xffffffffu, mt1, 2));
        const float nm0 = fmaxf(m0, mt0);
        const float nm1 = fmaxf(m1, mt1);
        const float sc0 = exp2f(m0 - nm0);
        const float sc1 = exp2f(m1 - nm1);
        m0 = nm0; m1 = nm1;

        float ls0 = 0.f, ls1 = 0.f;
#pragma unroll
        for (int nf = 0; nf < 8; nf++) {
            float p0 = exp2f(sa[nf][0] - nm0);
            float p1 = exp2f(sa[nf][1] - nm0);
            float p2 = exp2f(sa[nf][2] - nm1);
            float p3 = exp2f(sa[nf][3] - nm1);
            ls0 += p0 + p1;
            ls1 += p2 + p3;
            float2 lo = make_float2(__uint_as_float(f2tf32(p0)),
                                    __uint_as_float(f2tf32(p1)));
            float2 hi = make_float2(__uint_as_float(f2tf32(p2)),
                                    __uint_as_float(f2tf32(p3)));
            *reinterpret_cast<float2*>(&Ps[r0 * AP + 8 * nf + 2 * tk]) = lo;
            *reinterpret_cast<float2*>(&Ps[(r0 + 8) * AP + 8 * nf + 2 * tk]) = hi;
            of[nf][0] *= sc0; of[nf][1] *= sc0;
            of[nf][2] *= sc1; of[nf][3] *= sc1;
        }
        ls0 += __shfl_xor_sync(0xffffffffu, ls0, 1);
        ls0 += __shfl_xor_sync(0xffffffffu, ls0, 2);
        ls1 += __shfl_xor_sync(0xffffffffu, ls1, 1);
        ls1 += __shfl_xor_sync(0xffffffffu, ls1, 2);
        l0 = l0 * sc0 + ls0;
        l1 = l1 * sc1 + ls1;
        __syncwarp();

        // O += P V  (n = d)
#pragma unroll
        for (int ks = 0; ks < 8; ks++) {
            const int kk = ks * 8;
            uint32_t af[4];
            af[0] = __float_as_uint(Ps[r0 * AP + kk + tk]);
            af[1] = __float_as_uint(Ps[(r0 + 8) * AP + kk + tk]);
            af[2] = __float_as_uint(Ps[r0 * AP + kk + tk + 4]);
            af[3] = __float_as_uint(Ps[(r0 + 8) * AP + kk + tk + 4]);
#pragma unroll
            for (int nf = 0; nf < 8; nf++) {
                uint32_t bf[2];
                bf[0] = f2tf32(Vt[(8 * nf + grp) * AP + kk + tk]);
                bf[1] = f2tf32(Vt[(8 * nf + grp) * AP + kk + tk + 4]);
                mma_tf32(of[nf], af, bf);
            }
        }
    }

    // Epilogue.
    const float inv0 = 1.f / l0;
    const float inv1 = 1.f / l1;
    float* g0 = out + ((size_t)(b * T_) + q0 + r0) * (NQ * HD) + h * HD;
    float* g1 = g0 + 8 * (NQ * HD);
#pragma unroll
    for (int nf = 0; nf < 8; nf++) {
        int c = 8 * nf + 2 * tk;
        *reinterpret_cast<float2*>(g0 + c) =
            make_float2(of[nf][0] * inv0, of[nf][1] * inv0);
        *reinterpret_cast<float2*>(g1 + c) =
            make_float2(of[nf][2] * inv1, of[nf][3] * inv1);
    }
}

// ============================ Launch ============================
extern "C" void kernel_launch(void* const* d_in, const int* in_sizes, int n_in,
                              void* d_out, int out_size) {
    (void)in_sizes; (void)n_in; (void)out_size;
    const float* x = (const float*)d_in[0];
    const float* Wq = (const float*)d_in[1];
    const float* Wk = (const float*)d_in[2];
    const float* Wv = (const float*)d_in[3];
    float* out = (float*)d_out;

    float *Qp = nullptr, *Kp = nullptr, *Vp = nullptr, *Wt = nullptr;
    cudaGetSymbolAddress((void**)&Qp, g_Q);
    cudaGetSymbolAddress((void**)&Kp, g_K);
    cudaGetSymbolAddress((void**)&Vp, g_V);
    cudaGetSymbolAddress((void**)&Wt, g_Wt);
    float* Wtq = Wt;
    float* Wtk = Wt + (size_t)2048 * 2048;
    float* Wtv = Wtk + (size_t)512 * 2048;

    transpose_kernel<<<dim3(2048 / 32, 2048 / 32), dim3(32, 8)>>>(Wq, Wtq, 2048);
    transpose_kernel<<<dim3(512 / 32, 2048 / 32), dim3(32, 8)>>>(Wk, Wtk, 512);
    transpose_kernel<<<dim3(512 / 32, 2048 / 32), dim3(32, 8)>>>(Wv, Wtv, 512);

    gemm_mma<<<dim3(2048 / BN, ROWS / BM), 256>>>(x, Wtq, Qp, 2048);
    gemm_mma<<<dim3(512 / BN, ROWS / BM), 256>>>(x, Wtk, Kp, 512);
    gemm_mma<<<dim3(512 / BN, ROWS / BM), 256>>>(x, Wtv, Vp, 512);

    const int smem_attn = 3 * 64 * AP * sizeof(float);  // 52224 B
    cudaFuncSetAttribute(attn_mma, cudaFuncAttributeMaxDynamicSharedMemorySize,
                         smem_attn);
    dim3 ga(T_ / 64, NQ, B_);
    attn_mma<<<ga, 128, smem_attn>>>(Qp, Kp, Vp, out);
}

// round 5
// speedup vs baseline: 4.1873x; 1.2802x over previous
#include <cuda_runtime.h>
#include <math.h>
#include <stdint.h>

#define D_MODEL 2048
#define NQ 32
#define NKV 8
#define HD 64
#define B_ 2
#define T_ 2048
#define ROWS (B_ * T_)
#define KVS 1024   // combined K|V row stride

// Scratch (allocation-free device globals).
__device__ float g_Q[(size_t)ROWS * NQ * HD];    // [4096, 2048]
__device__ float g_KV[(size_t)ROWS * KVS];       // [4096, 1024]: K cols 0..511, V cols 512..1023
__device__ float g_Wt[(size_t)2048 * 2048 + (size_t)1024 * 2048];

__device__ __forceinline__ uint32_t f2tf32(float f) {
    uint32_t r;
    asm("cvt.rna.tf32.f32 %0, %1;" : "=r"(r) : "f"(f));
    return r;
}
__device__ __forceinline__ float4 cvt4f(float4 f) {
    float4 u;
    u.x = __uint_as_float(f2tf32(f.x));
    u.y = __uint_as_float(f2tf32(f.y));
    u.z = __uint_as_float(f2tf32(f.z));
    u.w = __uint_as_float(f2tf32(f.w));
    return u;
}

__device__ __forceinline__ void mma_tf32(float* d, const uint32_t* a,
                                         const uint32_t* b) {
    asm volatile(
        "mma.sync.aligned.m16n8k8.row.col.f32.tf32.tf32.f32 "
        "{%0,%1,%2,%3}, {%4,%5,%6,%7}, {%8,%9}, {%0,%1,%2,%3};"
        : "+f"(d[0]), "+f"(d[1]), "+f"(d[2]), "+f"(d[3])
        : "r"(a[0]), "r"(a[1]), "r"(a[2]), "r"(a[3]),
          "r"(b[0]), "r"(b[1]));
}

// ============================ Transpose ============================
__global__ __launch_bounds__(256) void transpose_kernel(
    const float* __restrict__ W, float* __restrict__ Wt, int N) {
    __shared__ float t[32][33];
    const int bx = blockIdx.x * 32;
    const int by = blockIdx.y * 32;
    const int x = threadIdx.x;
    const int y = threadIdx.y;
#pragma unroll
    for (int i = 0; i < 32; i += 8)
        t[y + i][x] = W[(size_t)(by + y + i) * N + bx + x];
    __syncthreads();
#pragma unroll
    for (int i = 0; i < 32; i += 8)
        Wt[(size_t)(bx + y + i) * 2048 + by + x] = t[x][y + i];
}

// ============================ mma.sync tf32 GEMM (double-buffered) ===========
#define BM 128
#define BN 128
#define BK 32
#define PITCH 36
#define NCH (D_MODEL / BK)

__global__ __launch_bounds__(256) void gemm_mma(
    const float* __restrict__ A, const float* __restrict__ Bt,
    float* __restrict__ C, int N) {
    __shared__ float As[2][BM][PITCH];
    __shared__ float Bs[2][BN][PITCH];

    const int tid = threadIdx.x;
    const int lane = tid & 31;
    const int warp = tid >> 5;
    const int wm = warp & 1;
    const int wn = warp >> 1;
    const int m0 = blockIdx.y * BM;
    const int n0 = blockIdx.x * BN;
    const int grp = lane >> 2;
    const int tk = lane & 3;
    const int lr = tid >> 3;   // load row 0..31 step: idx>>3
    const int lq = tid & 7;    // k-quad

    float acc[4][4][4];
#pragma unroll
    for (int i = 0; i < 4; i++)
#pragma unroll
        for (int j = 0; j < 4; j++)
#pragma unroll
            for (int v = 0; v < 4; v++) acc[i][j][v] = 0.f;

    float4 pa[4], pb[4];
    // Prologue: load chunk 0.
#pragma unroll
    for (int i = 0; i < 4; i++) {
        int r = i * 32 + lr;
        pa[i] = *reinterpret_cast<const float4*>(
            A + (size_t)(m0 + r) * D_MODEL + lq * 4);
        pb[i] = *reinterpret_cast<const float4*>(
            Bt + (size_t)(n0 + r) * D_MODEL + lq * 4);
    }
#pragma unroll
    for (int i = 0; i < 4; i++) {
        int r = i * 32 + lr;
        *reinterpret_cast<float4*>(&As[0][r][lq * 4]) = cvt4f(pa[i]);
        *reinterpret_cast<float4*>(&Bs[0][r][lq * 4]) = cvt4f(pb[i]);
    }
    __syncthreads();

    for (int c = 0; c < NCH; c++) {
        const int p = c & 1;
        // Prefetch next chunk (global -> regs), hidden under MMAs.
        if (c + 1 < NCH) {
            const int k0 = (c + 1) * BK;
#pragma unroll
            for (int i = 0; i < 4; i++) {
                int r = i * 32 + lr;
                pa[i] = *reinterpret_cast<const float4*>(
                    A + (size_t)(m0 + r) * D_MODEL + k0 + lq * 4);
                pb[i] = *reinterpret_cast<const float4*>(
                    Bt + (size_t)(n0 + r) * D_MODEL + k0 + lq * 4);
            }
        }

#pragma unroll
        for (int ks = 0; ks < 4; ks++) {
            const int kk = ks * 8;
            uint32_t a[4][4], b[4][2];
#pragma unroll
            for (int mf = 0; mf < 4; mf++) {
                int r = wm * 64 + mf * 16 + grp;
                a[mf][0] = __float_as_uint(As[p][r][kk + tk]);
                a[mf][1] = __float_as_uint(As[p][r + 8][kk + tk]);
                a[mf][2] = __float_as_uint(As[p][r][kk + tk + 4]);
                a[mf][3] = __float_as_uint(As[p][r + 8][kk + tk + 4]);
            }
#pragma unroll
            for (int nf = 0; nf < 4; nf++) {
                int cn = wn * 32 + nf * 8 + grp;
                b[nf][0] = __float_as_uint(Bs[p][cn][kk + tk]);
                b[nf][1] = __float_as_uint(Bs[p][cn][kk + tk + 4]);
            }
#pragma unroll
            for (int mf = 0; mf < 4; mf++)
#pragma unroll
                for (int nf = 0; nf < 4; nf++)
                    mma_tf32(acc[mf][nf], a[mf], b[nf]);
        }

        if (c + 1 < NCH) {
#pragma unroll
            for (int i = 0; i < 4; i++) {
                int r = i * 32 + lr;
                *reinterpret_cast<float4*>(&As[p ^ 1][r][lq * 4]) = cvt4f(pa[i]);
                *reinterpret_cast<float4*>(&Bs[p ^ 1][r][lq * 4]) = cvt4f(pb[i]);
            }
            __syncthreads();
        }
    }

#pragma unroll
    for (int mf = 0; mf < 4; mf++) {
#pragma unroll
        for (int nf = 0; nf < 4; nf++) {
            int r = m0 + wm * 64 + mf * 16 + grp;
            int c = n0 + wn * 32 + nf * 8 + 2 * tk;
            float2 lo = make_float2(acc[mf][nf][0], acc[mf][nf][1]);
            float2 hi = make_float2(acc[mf][nf][2], acc[mf][nf][3]);
            *reinterpret_cast<float2*>(C + (size_t)r * N + c) = lo;
            *reinterpret_cast<float2*>(C + (size_t)(r + 8) * N + c) = hi;
        }
    }
}

// ============================ Tensor-core attention ============================
// 128 threads (4 warps), 64-query tile; warp w owns rows 16w..16w+15.
// K/V pre-converted to tf32 at smem-store time. V row-major pitch 72.
#define APK 68
#define APV 72

__global__ __launch_bounds__(128) void attn_mma(
    const float* __restrict__ Q, const float* __restrict__ KV,
    float* __restrict__ out) {
    extern __shared__ float sm[];
    float* Ks = sm;                        // [64][APK] tf32 bits, [key][d]
    float* Vs = sm + 64 * APK;             // [64][APV] tf32 bits, [key][d]
    float* Ps = sm + 64 * (APK + APV);     // [64][APK] tf32 bits, [q][key]

    const int qt = blockIdx.x;
    const int h = blockIdx.y;
    const int b = blockIdx.z;
    const int kvh = h >> 2;
    const int tid = threadIdx.x;
    const int lane = tid & 31;
    const int w = tid >> 5;
    const int grp = lane >> 2;
    const int tk = lane & 3;
    const int q0 = qt * 64;
    const int r0 = 16 * w + grp;

    const float sc = 0.125f * 1.4426950408889634f;
    uint32_t qf[8][4];
    {
        const float* qr0 = Q + ((size_t)(b * T_) + q0 + r0) * (NQ * HD) + h * HD;
        const float* qr1 = qr0 + 8 * (NQ * HD);
#pragma unroll
        for (int ks = 0; ks < 8; ks++) {
            qf[ks][0] = f2tf32(qr0[ks * 8 + tk] * sc);
            qf[ks][1] = f2tf32(qr1[ks * 8 + tk] * sc);
            qf[ks][2] = f2tf32(qr0[ks * 8 + tk + 4] * sc);
            qf[ks][3] = f2tf32(qr1[ks * 8 + tk + 4] * sc);
        }
    }

    float of[8][4];
#pragma unroll
    for (int nf = 0; nf < 8; nf++)
#pragma unroll
        for (int v = 0; v < 4; v++) of[nf][v] = 0.f;
    float m0 = -1e30f, m1 = -1e30f, l0 = 0.f, l1 = 0.f;

    const float* kb = KV + (size_t)(b * T_) * KVS + kvh * HD;
    const float* vb = kb + 512;

    for (int jt = 0; jt <= qt; jt++) {
        __syncthreads();
#pragma unroll
        for (int i = 0; i < 8; i++) {
            int idx = i * 128 + tid;
            int key = idx >> 4;
            int q4 = idx & 15;
            size_t go = (size_t)(jt * 64 + key) * KVS + q4 * 4;
            float4 kv = *reinterpret_cast<const float4*>(kb + go);
            *reinterpret_cast<float4*>(&Ks[key * APK + q4 * 4]) = cvt4f(kv);
            float4 vv = *reinterpret_cast<const float4*>(vb + go);
            *reinterpret_cast<float4*>(&Vs[key * APV + q4 * 4]) = cvt4f(vv);
        }
        __syncthreads();

        // S = Q K^T
        float sa[8][4];
#pragma unroll
        for (int nf = 0; nf < 8; nf++)
#pragma unroll
            for (int v = 0; v < 4; v++) sa[nf][v] = 0.f;
#pragma unroll
        for (int ks = 0; ks < 8; ks++) {
            const int kk = ks * 8;
#pragma unroll
            for (int nf = 0; nf < 8; nf++) {
                uint32_t bf[2];
                bf[0] = __float_as_uint(Ks[(8 * nf + grp) * APK + kk + tk]);
                bf[1] = __float_as_uint(Ks[(8 * nf + grp) * APK + kk + tk + 4]);
                mma_tf32(sa[nf], qf[ks], bf);
            }
        }

        if (jt == qt) {
#pragma unroll
            for (int nf = 0; nf < 8; nf++) {
                int c0 = 8 * nf + 2 * tk;
                if (c0 > r0) sa[nf][0] = -1e30f;
                if (c0 + 1 > r0) sa[nf][1] = -1e30f;
                if (c0 > r0 + 8) sa[nf][2] = -1e30f;
                if (c0 + 1 > r0 + 8) sa[nf][3] = -1e30f;
            }
        }

        float mt0 = -1e30f, mt1 = -1e30f;
#pragma unroll
        for (int nf = 0; nf < 8; nf++) {
            mt0 = fmaxf(mt0, fmaxf(sa[nf][0], sa[nf][1]));
            mt1 = fmaxf(mt1, fmaxf(sa[nf][2], sa[nf][3]));
        }
        mt0 = fmaxf(mt0, __shfl_xor_sync(0xffffffffu, mt0, 1));
        mt0 = fmaxf(mt0, __shfl_xor_sync(0xffffffffu, mt0, 2));
        mt1 = fmaxf(mt1, __shfl_xor_sync(0xffffffffu, mt1, 1));
        mt1 = fmaxf(mt1, __shfl_xor_sync(0xffffffffu, mt1, 2));
        const float nm0 = fmaxf(m0, mt0);
        const float nm1 = fmaxf(m1, mt1);
        const float sc0 = exp2f(m0 - nm0);
        const float sc1 = exp2f(m1 - nm1);
        m0 = nm0; m1 = nm1;

        float ls0 = 0.f, ls1 = 0.f;
#pragma unroll
        for (int nf = 0; nf < 8; nf++) {
            float p0 = exp2f(sa[nf][0] - nm0);
            float p1 = exp2f(sa[nf][1] - nm0);
            float p2 = exp2f(sa[nf][2] - nm1);
            float p3 = exp2f(sa[nf][3] - nm1);
            ls0 += p0 + p1;
            ls1 += p2 + p3;
            float2 lo = make_float2(__uint_as_float(f2tf32(p0)),
                                    __uint_as_float(f2tf32(p1)));
            float2 hi = make_float2(__uint_as_float(f2tf32(p2)),
                                    __uint_as_float(f2tf32(p3)));
            *reinterpret_cast<float2*>(&Ps[r0 * APK + 8 * nf + 2 * tk]) = lo;
            *reinterpret_cast<float2*>(&Ps[(r0 + 8) * APK + 8 * nf + 2 * tk]) = hi;
            of[nf][0] *= sc0; of[nf][1] *= sc0;
            of[nf][2] *= sc1; of[nf][3] *= sc1;
        }
        ls0 += __shfl_xor_sync(0xffffffffu, ls0, 1);
        ls0 += __shfl_xor_sync(0xffffffffu, ls0, 2);
        ls1 += __shfl_xor_sync(0xffffffffu, ls1, 1);
        ls1 += __shfl_xor_sync(0xffffffffu, ls1, 2);
        l0 = l0 * sc0 + ls0;
        l1 = l1 * sc1 + ls1;
        __syncwarp();

        // O += P V
#pragma unroll
        for (int ks = 0; ks < 8; ks++) {
            const int kk = ks * 8;
            uint32_t af[4];
            af[0] = __float_as_uint(Ps[r0 * APK + kk + tk]);
            af[1] = __float_as_uint(Ps[(r0 + 8) * APK + kk + tk]);
            af[2] = __float_as_uint(Ps[r0 * APK + kk + tk + 4]);
            af[3] = __float_as_uint(Ps[(r0 + 8) * APK + kk + tk + 4]);
#pragma unroll
            for (int nf = 0; nf < 8; nf++) {
                uint32_t bf[2];
                bf[0] = __float_as_uint(Vs[(kk + tk) * APV + 8 * nf + grp]);
                bf[1] = __float_as_uint(Vs[(kk + tk + 4) * APV + 8 * nf + grp]);
                mma_tf32(of[nf], af, bf);
            }
        }
    }

    const float inv0 = 1.f / l0;
    const float inv1 = 1.f / l1;
    float* g0 = out + ((size_t)(b * T_) + q0 + r0) * (NQ * HD) + h * HD;
    float* g1 = g0 + 8 * (NQ * HD);
#pragma unroll
    for (int nf = 0; nf < 8; nf++) {
        int c = 8 * nf + 2 * tk;
        *reinterpret_cast<float2*>(g0 + c) =
            make_float2(of[nf][0] * inv0, of[nf][1] * inv0);
        *reinterpret_cast<float2*>(g1 + c) =
            make_float2(of[nf][2] * inv1, of[nf][3] * inv1);
    }
}

// ============================ Launch ============================
extern "C" void kernel_launch(void* const* d_in, const int* in_sizes, int n_in,
                              void* d_out, int out_size) {
    (void)in_sizes; (void)n_in; (void)out_size;
    const float* x = (const float*)d_in[0];
    const float* Wq = (const float*)d_in[1];
    const float* Wk = (const float*)d_in[2];
    const float* Wv = (const float*)d_in[3];
    float* out = (float*)d_out;

    float *Qp = nullptr, *KVp = nullptr, *Wt = nullptr;
    cudaGetSymbolAddress((void**)&Qp, g_Q);
    cudaGetSymbolAddress((void**)&KVp, g_KV);
    cudaGetSymbolAddress((void**)&Wt, g_Wt);
    float* Wtq = Wt;
    float* Wtkv = Wt + (size_t)2048 * 2048;   // rows 0..511 = Wk^T, 512..1023 = Wv^T

    transpose_kernel<<<dim3(2048 / 32, 2048 / 32), dim3(32, 8)>>>(Wq, Wtq, 2048);
    transpose_kernel<<<dim3(512 / 32, 2048 / 32), dim3(32, 8)>>>(Wk, Wtkv, 512);
    transpose_kernel<<<dim3(512 / 32, 2048 / 32), dim3(32, 8)>>>(
        Wv, Wtkv + (size_t)512 * 2048, 512);

    gemm_mma<<<dim3(2048 / BN, ROWS / BM), 256>>>(x, Wtq, Qp, 2048);
    gemm_mma<<<dim3(KVS / BN, ROWS / BM), 256>>>(x, Wtkv, KVp, KVS);

    const int smem_attn = 64 * (APK + APV + APK) * sizeof(float);  // 53248 B
    cudaFuncSetAttribute(attn_mma, cudaFuncAttributeMaxDynamicSharedMemorySize,
                         smem_attn);
    dim3 ga(T_ / 64, NQ, B_);
    attn_mma<<<ga, 128, smem_attn>>>(Qp, KVp, out);
}

// round 7
// speedup vs baseline: 7.6681x; 1.8313x over previous
#include <cuda_runtime.h>
#include <cuda_fp16.h>
#include <math.h>
#include <stdint.h>

#define D_MODEL 2048
#define NQ 32
#define NKV 8
#define HD 64
#define B_ 2
#define T_ 2048
#define ROWS (B_ * T_)
#define KVS 1024

// Scratch (allocation-free device globals), all fp16.
__device__ __half g_xh[(size_t)ROWS * D_MODEL];          // x in half
__device__ __half g_Qh[(size_t)ROWS * NQ * HD];          // Q (pre-scaled)
__device__ __half g_KVh[(size_t)ROWS * KVS];             // K|V
__device__ __half g_Wth[(size_t)(2048 + 1024) * 2048];   // Wq^T | (Wk^T;Wv^T)

// ============================ PTX helpers ============================
__device__ __forceinline__ uint32_t smem_u32(const void* p) {
    uint32_t a;
    asm("{ .reg .u64 t; cvta.to.shared.u64 t, %1; cvt.u32.u64 %0, t; }"
        : "=r"(a) : "l"(p));
    return a;
}
#define CP16(dst, src) \
    asm volatile("cp.async.cg.shared.global [%0], [%1], 16;" \
                 :: "r"(dst), "l"(src))
#define CP_COMMIT() asm volatile("cp.async.commit_group;" ::: "memory")
#define CP_WAIT0() asm volatile("cp.async.wait_group 0;" ::: "memory")
#define CP_WAIT1() asm volatile("cp.async.wait_group 1;" ::: "memory")

__device__ __forceinline__ void ldm_x4(uint32_t* r, uint32_t a) {
    asm volatile("ldmatrix.sync.aligned.m8n8.x4.shared.b16 {%0,%1,%2,%3}, [%4];"
                 : "=r"(r[0]), "=r"(r[1]), "=r"(r[2]), "=r"(r[3]) : "r"(a));
}
__device__ __forceinline__ void ldm_x4t(uint32_t* r, uint32_t a) {
    asm volatile(
        "ldmatrix.sync.aligned.m8n8.x4.trans.shared.b16 {%0,%1,%2,%3}, [%4];"
        : "=r"(r[0]), "=r"(r[1]), "=r"(r[2]), "=r"(r[3]) : "r"(a));
}
__device__ __forceinline__ void mma_f16(float* d, const uint32_t* a,
                                        const uint32_t* b) {
    asm volatile(
        "mma.sync.aligned.m16n8k16.row.col.f32.f16.f16.f32 "
        "{%0,%1,%2,%3}, {%4,%5,%6,%7}, {%8,%9}, {%0,%1,%2,%3};"
        : "+f"(d[0]), "+f"(d[1]), "+f"(d[2]), "+f"(d[3])
        : "r"(a[0]), "r"(a[1]), "r"(a[2]), "r"(a[3]), "r"(b[0]), "r"(b[1]));
}

// ============================ x -> half ============================
__global__ __launch_bounds__(256) void cvt_x(const float* __restrict__ x,
                                             __half* __restrict__ xh) {
    int i = (blockIdx.x * 256 + threadIdx.x) * 4;
    float4 v = *reinterpret_cast<const float4*>(x + i);
    *reinterpret_cast<__half2*>(xh + i) = __floats2half2_rn(v.x, v.y);
    *reinterpret_cast<__half2*>(xh + i + 2) = __floats2half2_rn(v.z, v.w);
}

// ============================ W transpose -> half ============================
__global__ __launch_bounds__(256) void transpose_wh(
    const float* __restrict__ W, __half* __restrict__ Wt, int N, float scale) {
    __shared__ float t[32][33];
    const int bx = blockIdx.x * 32;
    const int by = blockIdx.y * 32;
    const int x = threadIdx.x;
    const int y = threadIdx.y;
#pragma unroll
    for (int i = 0; i < 32; i += 8)
        t[y + i][x] = W[(size_t)(by + y + i) * N + bx + x];
    __syncthreads();
#pragma unroll
    for (int i = 0; i < 32; i += 8)
        Wt[(size_t)(bx + y + i) * 2048 + by + x] =
            __float2half_rn(t[x][y + i] * scale);
}

// ============================ fp16 GEMM ============================
// C_half[M][N] = Ah[M,2048] @ Wt[N,2048]^T. 128x128x32, cp.async 2-stage.
#define GP 40            // smem pitch (halves)
#define GBUF (128 * GP)
#define GNCH (D_MODEL / 32)

__global__ __launch_bounds__(256) void gemm_h(
    const __half* __restrict__ A, const __half* __restrict__ Bt,
    __half* __restrict__ C, int N) {
    __shared__ __half As[2][GBUF];
    __shared__ __half Bs[2][GBUF];

    const int tid = threadIdx.x;
    const int lane = tid & 31;
    const int warp = tid >> 5;
    const int wm = warp & 1;
    const int wn = warp >> 1;
    const int m0 = blockIdx.y * 128;
    const int n0 = blockIdx.x * 128;
    const int grp = lane >> 2;
    const int tk = lane & 3;
    const int l15 = lane & 15;
    const int lhi = lane >> 4;
    const int cr = tid >> 2;
    const int cq = tid & 3;

    const uint32_t a_s = smem_u32(As);
    const uint32_t b_s = smem_u32(Bs);
    const char* Ag = (const char*)(A + (size_t)m0 * D_MODEL);
    const char* Bg = (const char*)(Bt + (size_t)n0 * D_MODEL);

    float acc[4][4][4];
#pragma unroll
    for (int i = 0; i < 4; i++)
#pragma unroll
        for (int j = 0; j < 4; j++)
#pragma unroll
            for (int v = 0; v < 4; v++) acc[i][j][v] = 0.f;

#pragma unroll
    for (int i = 0; i < 2; i++) {
        int r = i * 64 + cr;
        CP16(a_s + r * 80 + cq * 16, Ag + (size_t)r * 4096 + cq * 16);
        CP16(b_s + r * 80 + cq * 16, Bg + (size_t)r * 4096 + cq * 16);
    }
    CP_COMMIT();

    for (int c = 0; c < GNCH; c++) {
        if (c + 1 < GNCH) {
            const uint32_t po = ((c + 1) & 1) * (GBUF * 2);
            const size_t ko = (size_t)(c + 1) * 64;
#pragma unroll
            for (int i = 0; i < 2; i++) {
                int r = i * 64 + cr;
                CP16(a_s + po + r * 80 + cq * 16,
                     Ag + (size_t)r * 4096 + ko + cq * 16);
                CP16(b_s + po + r * 80 + cq * 16,
                     Bg + (size_t)r * 4096 + ko + cq * 16);
            }
            CP_COMMIT();
            CP_WAIT1();
        } else {
            CP_WAIT0();
        }
        __syncthreads();

        const uint32_t ab = a_s + (c & 1) * (GBUF * 2);
        const uint32_t bb = b_s + (c & 1) * (GBUF * 2);
#pragma unroll
        for (int ks = 0; ks < 2; ks++) {
            uint32_t a[4][4], bq[2][4];
#pragma unroll
            for (int mf = 0; mf < 4; mf++)
                ldm_x4(a[mf], ab + (wm * 64 + mf * 16 + l15) * 80 + lhi * 16 +
                                  ks * 32);
            // B tile is [n][k] row-major -> NON-trans ldmatrix for B-frag.
#pragma unroll
            for (int nh = 0; nh < 2; nh++)
                ldm_x4(bq[nh], bb + (wn * 32 + nh * 16 + l15) * 80 +
                                   lhi * 16 + ks * 32);
#pragma unroll
            for (int mf = 0; mf < 4; mf++)
#pragma unroll
                for (int nf = 0; nf < 4; nf++) {
                    uint32_t b2[2] = {bq[nf >> 1][nf & 1],
                                      bq[nf >> 1][2 + (nf & 1)]};
                    mma_f16(acc[mf][nf], a[mf], b2);
                }
        }
        __syncthreads();
    }

#pragma unroll
    for (int mf = 0; mf < 4; mf++) {
#pragma unroll
        for (int nf = 0; nf < 4; nf++) {
            int r = m0 + wm * 64 + mf * 16 + grp;
            int cc = n0 + wn * 32 + nf * 8 + 2 * tk;
            *reinterpret_cast<__half2*>(C + (size_t)r * N + cc) =
                __floats2half2_rn(acc[mf][nf][0], acc[mf][nf][1]);
            *reinterpret_cast<__half2*>(C + (size_t)(r + 8) * N + cc) =
                __floats2half2_rn(acc[mf][nf][2], acc[mf][nf][3]);
        }
    }
}

// ============================ fp16 attention ============================
// 128 threads (4 warps), 64-query tile. cp.async double-buffered K/V tiles.
// K tile [key][d]: non-trans B-frags. V tile [key][d]: trans B-frags (k=key).
#define ATP 72
#define ATB (64 * ATP)

__global__ __launch_bounds__(128) void attn_h(
    const __half* __restrict__ Qh, const __half* __restrict__ KVh,
    float* __restrict__ out) {
    __shared__ __half Ks[2][ATB];
    __shared__ __half Vs[2][ATB];
    __shared__ __half Ps[ATB];

    const int qt = blockIdx.x;
    const int h = blockIdx.y;
    const int b = blockIdx.z;
    const int kvh = h >> 2;
    const int tid = threadIdx.x;
    const int lane = tid & 31;
    const int w = tid >> 5;
    const int grp = lane >> 2;
    const int tk = lane & 3;
    const int l15 = lane & 15;
    const int lhi = lane >> 4;
    const int q0 = qt * 64;
    const int r0 = 16 * w + grp;

    const uint32_t k_s = smem_u32(Ks);
    const uint32_t v_s = smem_u32(Vs);
    const uint32_t p_s = smem_u32(Ps);

    uint32_t qf[4][4];
    {
        const __half* qb0 =
            Qh + ((size_t)(b * T_) + q0 + r0) * (NQ * HD) + h * HD;
        const __half* qb1 = qb0 + 8 * (NQ * HD);
#pragma unroll
        for (int ks = 0; ks < 4; ks++) {
            qf[ks][0] = *(const uint32_t*)(qb0 + 16 * ks + 2 * tk);
            qf[ks][1] = *(const uint32_t*)(qb1 + 16 * ks + 2 * tk);
            qf[ks][2] = *(const uint32_t*)(qb0 + 16 * ks + 2 * tk + 8);
            qf[ks][3] = *(const uint32_t*)(qb1 + 16 * ks + 2 * tk + 8);
        }
    }

    float of[8][4];
#pragma unroll
    for (int nf = 0; nf < 8; nf++)
#pragma unroll
        for (int v = 0; v < 4; v++) of[nf][v] = 0.f;
    float m0 = -1e30f, m1 = -1e30f, l0 = 0.f, l1 = 0.f;

    const char* kg = (const char*)(KVh + (size_t)(b * T_) * KVS + kvh * HD);
    const char* vg = (const char*)(KVh + (size_t)(b * T_) * KVS + 512 +
                                   kvh * HD);
    const int crow = tid >> 3;
    const int cq8 = tid & 7;

#pragma unroll
    for (int i = 0; i < 4; i++) {
        int rr = i * 16 + crow;
        CP16(k_s + rr * 144 + cq8 * 16, kg + (size_t)rr * 2048 + cq8 * 16);
        CP16(v_s + rr * 144 + cq8 * 16, vg + (size_t)rr * 2048 + cq8 * 16);
    }
    CP_COMMIT();

    for (int jt = 0; jt <= qt; jt++) {
        if (jt < qt) {
            const uint32_t po = ((jt + 1) & 1) * (ATB * 2);
            const size_t kko = (size_t)(jt + 1) * 64 * 2048;
#pragma unroll
            for (int i = 0; i < 4; i++) {
                int rr = i * 16 + crow;
                CP16(k_s + po + rr * 144 + cq8 * 16,
                     kg + (size_t)rr * 2048 + kko + cq8 * 16);
                CP16(v_s + po + rr * 144 + cq8 * 16,
                     vg + (size_t)rr * 2048 + kko + cq8 * 16);
            }
            CP_COMMIT();
            CP_WAIT1();
        } else {
            CP_WAIT0();
        }
        __syncthreads();

        const uint32_t kb = k_s + (jt & 1) * (ATB * 2);
        const uint32_t vb = v_s + (jt & 1) * (ATB * 2);

        // S = Q K^T  (K tile [n=key][k=d] -> non-trans B-frags)
        float sa[8][4];
#pragma unroll
        for (int nf = 0; nf < 8; nf++)
#pragma unroll
            for (int v = 0; v < 4; v++) sa[nf][v] = 0.f;
#pragma unroll
        for (int ks = 0; ks < 4; ks++) {
            uint32_t kq[4][4];
#pragma unroll
            for (int nh = 0; nh < 4; nh++)
                ldm_x4(kq[nh],
                       kb + (nh * 16 + l15) * 144 + lhi * 16 + ks * 32);
#pragma unroll
            for (int nf = 0; nf < 8; nf++) {
                uint32_t b2[2] = {kq[nf >> 1][nf & 1],
                                  kq[nf >> 1][2 + (nf & 1)]};
                mma_f16(sa[nf], qf[ks], b2);
            }
        }

        if (jt == qt) {
#pragma unroll
            for (int nf = 0; nf < 8; nf++) {
                int c0 = 8 * nf + 2 * tk;
                if (c0 > r0) sa[nf][0] = -1e30f;
                if (c0 + 1 > r0) sa[nf][1] = -1e30f;
                if (c0 > r0 + 8) sa[nf][2] = -1e30f;
                if (c0 + 1 > r0 + 8) sa[nf][3] = -1e30f;
            }
        }

        float mt0 = -1e30f, mt1 = -1e30f;
#pragma unroll
        for (int nf = 0; nf < 8; nf++) {
            mt0 = fmaxf(mt0, fmaxf(sa[nf][0], sa[nf][1]));
            mt1 = fmaxf(mt1, fmaxf(sa[nf][2], sa[nf][3]));
        }
        mt0 = fmaxf(mt0, __shfl_xor_sync(0xffffffffu, mt0, 1));
        mt0 = fmaxf(mt0, __shfl_xor_sync(0xffffffffu, mt0, 2));
        mt1 = fmaxf(mt1, __shfl_xor_sync(0xffffffffu, mt1, 1));
        mt1 = fmaxf(mt1, __shfl_xor_sync(0xffffffffu, mt1, 2));
        const float nm0 = fmaxf(m0, mt0);
        const float nm1 = fmaxf(m1, mt1);
        const float sc0 = exp2f(m0 - nm0);
        const float sc1 = exp2f(m1 - nm1);
        m0 = nm0; m1 = nm1;

        float ls0 = 0.f, ls1 = 0.f;
#pragma unroll
        for (int nf = 0; nf < 8; nf++) {
            float p0 = exp2f(sa[nf][0] - nm0);
            float p1 = exp2f(sa[nf][1] - nm0);
            float p2 = exp2f(sa[nf][2] - nm1);
            float p3 = exp2f(sa[nf][3] - nm1);
            ls0 += p0 + p1;
            ls1 += p2 + p3;
            *reinterpret_cast<__half2*>(
                &Ps[r0 * ATP + 8 * nf + 2 * tk]) = __floats2half2_rn(p0, p1);
            *reinterpret_cast<__half2*>(
                &Ps[(r0 + 8) * ATP + 8 * nf + 2 * tk]) =
                __floats2half2_rn(p2, p3);
            of[nf][0] *= sc0; of[nf][1] *= sc0;
            of[nf][2] *= sc1; of[nf][3] *= sc1;
        }
        ls0 += __shfl_xor_sync(0xffffffffu, ls0, 1);
        ls0 += __shfl_xor_sync(0xffffffffu, ls0, 2);
        ls1 += __shfl_xor_sync(0xffffffffu, ls1, 1);
        ls1 += __shfl_xor_sync(0xffffffffu, ls1, 2);
        l0 = l0 * sc0 + ls0;
        l1 = l1 * sc1 + ls1;
        __syncwarp();

        // O += P V  (V tile [k=key][n=d] -> trans B-frags; k chunk = ks)
#pragma unroll
        for (int ks = 0; ks < 4; ks++) {
            uint32_t pf[4];
            ldm_x4(pf, p_s + (16 * w + l15) * 144 + lhi * 16 + ks * 32);
            uint32_t vq[4][4];
#pragma unroll
            for (int dh = 0; dh < 4; dh++)
                ldm_x4t(vq[dh],
                        vb + (ks * 16 + l15) * 144 + lhi * 16 + dh * 32);
#pragma unroll
            for (int nf = 0; nf < 8; nf++) {
                uint32_t b2[2] = {vq[nf >> 1][2 * (nf & 1)],
                                  vq[nf >> 1][2 * (nf & 1) + 1]};
                mma_f16(of[nf], pf, b2);
            }
        }
        __syncthreads();
    }

    const float inv0 = 1.f / l0;
    const float inv1 = 1.f / l1;
    float* g0 = out + ((size_t)(b * T_) + q0 + r0) * (NQ * HD) + h * HD;
    float* g1 = g0 + 8 * (NQ * HD);
#pragma unroll
    for (int nf = 0; nf < 8; nf++) {
        int c = 8 * nf + 2 * tk;
        *reinterpret_cast<float2*>(g0 + c) =
            make_float2(of[nf][0] * inv0, of[nf][1] * inv0);
        *reinterpret_cast<float2*>(g1 + c) =
            make_float2(of[nf][2] * inv1, of[nf][3] * inv1);
    }
}

// ============================ Launch ============================
extern "C" void kernel_launch(void* const* d_in, const int* in_sizes, int n_in,
                              void* d_out, int out_size) {
    (void)in_sizes; (void)n_in; (void)out_size;
    const float* x = (const float*)d_in[0];
    const float* Wq = (const float*)d_in[1];
    const float* Wk = (const float*)d_in[2];
    const float* Wv = (const float*)d_in[3];
    float* out = (float*)d_out;

    __half *xh, *Qh, *KVh, *Wth;
    cudaGetSymbolAddress((void**)&xh, g_xh);
    cudaGetSymbolAddress((void**)&Qh, g_Qh);
    cudaGetSymbolAddress((void**)&KVh, g_KVh);
    cudaGetSymbolAddress((void**)&Wth, g_Wth);
    __half* Wthq = Wth;
    __half* Wthkv = Wth + (size_t)2048 * 2048;

    const float sc = 0.125f * 1.4426950408889634f;

    cvt_x<<<(ROWS * D_MODEL) / (256 * 4), 256>>>(x, xh);
    transpose_wh<<<dim3(64, 64), dim3(32, 8)>>>(Wq, Wthq, 2048, sc);
    transpose_wh<<<dim3(16, 64), dim3(32, 8)>>>(Wk, Wthkv, 512, 1.0f);
    transpose_wh<<<dim3(16, 64), dim3(32, 8)>>>(
        Wv, Wthkv + (size_t)512 * 2048, 512, 1.0f);

    gemm_h<<<dim3(16, 32), 256>>>(xh, Wthq, Qh, 2048);
    gemm_h<<<dim3(8, 32), 256>>>(xh, Wthkv, KVh, KVS);

    dim3 ga(T_ / 64, NQ, B_);
    attn_h<<<ga, 128>>>(Qh, KVh, out);
}